// round 2
// baseline (speedup 1.0000x reference)
#include <cuda_runtime.h>
#include <math_constants.h>

// ---------------- problem constants ----------------
#define NQ       8
#define KCB      2048
#define DIMX     512
#define BB       32
#define TT       1500
#define NV       (BB * TT)          // 48000 vectors
#define M_TILE   64
#define NBLK     (NV / M_TILE)      // 750 CTAs
#define QO_SIZE  (BB * DIMX * TT)   // 24,576,000
#define IDX_SIZE (BB * NQ * TT)     // 384,000

// main-kernel shared memory layout (bytes)
//   resT   [512][64] floats : 131072
//   cbs    [32*512]  floats :  65536
//   s_Ad   [256]     double :   2048   (also reused for loss reduction)
//   s_A    [64]      floats :    256
//   bestv  [64]      floats :    256
//   besti  [64]      ints   :    256
//   s_idx  [8][64]   ints   :   2048
#define SMEM_BYTES (131072 + 65536 + 2048 + 256 + 256 + 256 + 2048)

// ---------------- device scratch (no allocs allowed) ----------------
__device__ float  g_cbT[(size_t)NQ * DIMX * KCB];  // codebook transposed [q][d][k]
__device__ float  g_cn2[NQ * KCB];                 // ||c||^2 (full, fp32)
__device__ double g_losspart[NBLK];

// ---------------- f32x2 helpers (packed fp32, 2 independent fused FMAs) ----
__device__ __forceinline__ void fma2(unsigned long long& d,
                                     unsigned long long a,
                                     unsigned long long b) {
    asm("fma.rn.f32x2 %0, %1, %2, %0;" : "+l"(d) : "l"(a), "l"(b));
}
__device__ __forceinline__ unsigned long long pack2(float x, float y) {
    unsigned long long r;
    asm("mov.b64 %0, {%1, %2};" : "=l"(r) : "f"(x), "f"(y));
    return r;
}
__device__ __forceinline__ void unpack2(unsigned long long v, float& lo, float& hi) {
    asm("mov.b64 {%0, %1}, %2;" : "=f"(lo), "=f"(hi) : "l"(v));
}

// ---------------- kernel 1: codebook transpose [q][k][d] -> [q][d][k] ------
__global__ void k_transpose(const float* __restrict__ cb) {
    __shared__ float tile[32][33];
    int q  = blockIdx.z;
    int k0 = blockIdx.x * 32;
    int d0 = blockIdx.y * 32;
    int tx = threadIdx.x, ty = threadIdx.y;
    const float* src = cb + (size_t)q * KCB * DIMX;
#pragma unroll
    for (int i = 0; i < 4; ++i) {
        int k = k0 + ty + i * 8;
        tile[ty + i * 8][tx] = src[(size_t)k * DIMX + d0 + tx];
    }
    __syncthreads();
    float* dst = g_cbT + (size_t)q * DIMX * KCB;
#pragma unroll
    for (int i = 0; i < 4; ++i) {
        int d = d0 + ty + i * 8;
        dst[(size_t)d * KCB + k0 + tx] = tile[tx][ty + i * 8];
    }
}

// ---------------- kernel 2: full squared norms ||c||^2 ---------------------
// Any fp32-accurate order works: C's rounding error (~1e-12 abs) is far below
// the final-add grid (~3e-5); computed in double, rounded once to fp32.
__global__ void k_cn2(const float* __restrict__ cb) {
    int row  = blockIdx.x * 8 + (threadIdx.x >> 5);   // 0..16383 = q*2048+k
    int lane = threadIdx.x & 31;
    const float* src = cb + (size_t)row * DIMX;
    double s = 0.0;
#pragma unroll
    for (int t = 0; t < 16; ++t) {
        double v = (double)src[t * 32 + lane];
        s += v * v;
    }
#pragma unroll
    for (int o = 16; o; o >>= 1)
        s += __shfl_xor_sync(0xffffffffu, s, o);
    if (lane == 0) g_cn2[row] = (float)s;
}

// ---------------- kernel 3: main RVQ (all 8 stages per CTA tile) -----------
__global__ void __launch_bounds__(256, 1)
k_main(const float* __restrict__ x, const float* __restrict__ cb,
       float* __restrict__ out) {
    extern __shared__ float sm[];
    float*  resT    = sm;                          // [512][64] residual (T)
    float*  cbs     = sm + DIMX * M_TILE;          // [32][512] codebook chunk
    double* s_Ad    = (double*)(cbs + 32 * 512);   // [256] A partials / loss
    float*  s_A     = (float*)(s_Ad + 256);        // [64]  ||r||^2 per vector
    float*  s_bestv = s_A + 64;                    // [64]
    int*    s_besti = (int*)(s_bestv + 64);        // [64]
    int*    s_idx   = s_besti + 64;                // [8][64] index history

    const int tid  = threadIdx.x;
    const int lane = tid & 31;
    const int wid  = tid >> 5;        // 8 warps = 8 m-groups of 8 vectors
    const int n0   = blockIdx.x * M_TILE;
    const int m    = tid & 63;
    const int ds   = tid >> 6;        // 4 slices of 128 d

    // ---- init residual = x (transpose gather into smem) ----
    {
        int n = n0 + m;
        int b = n / TT;
        int t = n - b * TT;
        const float* xb = x + (size_t)b * DIMX * TT + t;
#pragma unroll 8
        for (int j = 0; j < 128; ++j) {
            int d = ds * 128 + j;
            resT[d * M_TILE + m] = xb[(size_t)d * TT];
        }
    }
    __syncthreads();

#pragma unroll 1
    for (int q = 0; q < NQ; ++q) {
        // ---- A = ||r||^2 per vector (double, rounded once; order-free) ----
        {
            const float* rcol = resT + (size_t)(ds * 128) * M_TILE + m;
            double p = 0.0;
#pragma unroll 8
            for (int j = 0; j < 128; ++j) {
                double v = (double)rcol[j * M_TILE];
                p += v * v;
            }
            s_Ad[tid] = p;
            if (tid < 64) { s_bestv[tid] = CUDART_INF_F; s_besti[tid] = 0; }
        }
        __syncthreads();
        if (tid < 64) {
            double a = ((s_Ad[tid] + s_Ad[64 + tid]) + s_Ad[128 + tid])
                       + s_Ad[192 + tid];
            s_A[tid] = (float)a;
        }
        // (s_A consumed only after the syncthreads inside the GEMM loop)

        const float* cbTq = g_cbT + (size_t)q * DIMX * KCB;
        const float* cn2q = g_cn2 + q * KCB;

#pragma unroll 1
        for (int kc = 0; kc < 4; ++kc) {           // 4 chunks of 512 codewords
            const int k0 = kc * 512;
            unsigned long long acc[8][8];          // 8 m x 8 k-pairs (16 k)
#pragma unroll
            for (int i = 0; i < 8; ++i)
#pragma unroll
                for (int j = 0; j < 8; ++j) acc[i][j] = 0ull;

#pragma unroll 1
            for (int dc = 0; dc < 16; ++dc) {      // 16 chunks of 32 dims, d ascending
                __syncthreads();
                {   // cooperative load cbs[32][512] <- cbT[q][dc*32 ..][k0 ..]
                    const float* src = cbTq + (size_t)(dc * 32) * KCB + k0;
#pragma unroll
                    for (int j = 0; j < 16; ++j) {
                        int idx = j * 1024 + tid * 4;
                        int row = idx >> 9;
                        int col = idx & 511;
                        float4 v = *(const float4*)(src + (size_t)row * KCB + col);
                        *(float4*)(cbs + idx) = v;
                    }
                }
                __syncthreads();

                const float* rbase = resT + (dc * 32) * M_TILE + wid * 8;
                const float* cbase = cbs + lane * 16;
#pragma unroll 1
                for (int dd = 0; dd < 32; ++dd) {
                    const float* rp = rbase + dd * M_TILE;
                    float4 ra = *(const float4*)rp;
                    float4 rb = *(const float4*)(rp + 4);
                    unsigned long long rr[8];
                    rr[0] = pack2(ra.x, ra.x); rr[1] = pack2(ra.y, ra.y);
                    rr[2] = pack2(ra.z, ra.z); rr[3] = pack2(ra.w, ra.w);
                    rr[4] = pack2(rb.x, rb.x); rr[5] = pack2(rb.y, rb.y);
                    rr[6] = pack2(rb.z, rb.z); rr[7] = pack2(rb.w, rb.w);

                    const ulonglong2* cp = (const ulonglong2*)(cbase + dd * 512);
                    ulonglong2 c01 = cp[0], c23 = cp[1], c45 = cp[2], c67 = cp[3];
                    unsigned long long cc[8] = {c01.x, c01.y, c23.x, c23.y,
                                                c45.x, c45.y, c67.x, c67.y};
#pragma unroll
                    for (int i = 0; i < 8; ++i)
#pragma unroll
                        for (int j = 0; j < 8; ++j)
                            fma2(acc[i][j], rr[i], cc[j]);
                }
            }

            // ---- finalize chunk: dist = fl(fl(A - 2B) + C); running argmin ----
            float cn[16];
            {
                const float4* c4 = (const float4*)(cn2q + k0 + lane * 16);
                float4 a = c4[0], b = c4[1], c = c4[2], d = c4[3];
                cn[0]=a.x; cn[1]=a.y; cn[2]=a.z; cn[3]=a.w;
                cn[4]=b.x; cn[5]=b.y; cn[6]=b.z; cn[7]=b.w;
                cn[8]=c.x; cn[9]=c.y; cn[10]=c.z; cn[11]=c.w;
                cn[12]=d.x; cn[13]=d.y; cn[14]=d.z; cn[15]=d.w;
            }
#pragma unroll
            for (int i = 0; i < 8; ++i) {
                float A  = s_A[wid * 8 + i];
                float bv = CUDART_INF_F;
                int   bi = 0;
#pragma unroll
                for (int j = 0; j < 8; ++j) {
                    float lo, hi;
                    unpack2(acc[i][j], lo, hi);
                    int k = k0 + lane * 16 + 2 * j;
                    // fl(2B) is exact, so fmaf(-2,B,A) == fl(A - fl(2B))
                    float v0 = __fadd_rn(__fmaf_rn(-2.0f, lo, A), cn[2 * j]);
                    if (v0 < bv) { bv = v0; bi = k; }
                    float v1 = __fadd_rn(__fmaf_rn(-2.0f, hi, A), cn[2 * j + 1]);
                    if (v1 < bv) { bv = v1; bi = k + 1; }
                }
#pragma unroll
                for (int o = 16; o; o >>= 1) {
                    float ov = __shfl_xor_sync(0xffffffffu, bv, o);
                    int   oi = __shfl_xor_sync(0xffffffffu, bi, o);
                    if (ov < bv || (ov == bv && oi < bi)) { bv = ov; bi = oi; }
                }
                if (lane == 0) {
                    int mm = wid * 8 + i;   // only this warp touches this m
                    if (bv < s_bestv[mm]) { s_bestv[mm] = bv; s_besti[mm] = bi; }
                }
            }
        }
        __syncthreads();

        // ---- record + emit indices for this stage ----
        if (tid < 64) {
            int n = n0 + tid;
            int b = n / TT;
            int t = n - b * TT;
            int bi = s_besti[tid];
            s_idx[q * 64 + tid] = bi;
            out[QO_SIZE + (size_t)b * NQ * TT + q * TT + t] = (float)bi;
        }
        __syncthreads();

        // ---- exact straight-through residual update ----
        //   t  = fl(c - r); qo = fl(r + t); r' = fl(r - qo)
        {
            const float* crow = cb + ((size_t)q * KCB + s_idx[q * 64 + m]) * DIMX
                                   + ds * 128;
            float* rcol = resT + (size_t)(ds * 128) * M_TILE + m;
#pragma unroll 4
            for (int j = 0; j < 32; ++j) {
                float4 c4 = *(const float4*)(crow + j * 4);
                int base = (j * 4) * M_TILE;
                float cv[4] = {c4.x, c4.y, c4.z, c4.w};
#pragma unroll
                for (int i = 0; i < 4; ++i) {
                    float r  = rcol[base + i * M_TILE];
                    float t  = __fsub_rn(cv[i], r);
                    float qo = __fadd_rn(r, t);
                    rcol[base + i * M_TILE] = __fsub_rn(r, qo);
                }
            }
        }
        __syncthreads();
    }

    // ---- final pass: replay the exact ST chain from x to build Q and loss ----
    double lsum = 0.0;
    {
        int n = n0 + m;
        int b = n / TT;
        int t = n - b * TT;
        const float* xb = x   + (size_t)b * DIMX * TT + t;
        float*       ob = out + (size_t)b * DIMX * TT + t;
#pragma unroll 2
        for (int j = 0; j < 128; ++j) {
            int d = ds * 128 + j;
            float r = xb[(size_t)d * TT];
            float Q = 0.0f;
#pragma unroll
            for (int q = 0; q < NQ; ++q) {
                float c  = cb[((size_t)q * KCB + s_idx[q * 64 + m]) * DIMX + d];
                float tq = __fsub_rn(c, r);
                float qo = __fadd_rn(r, tq);
                Q = __fadd_rn(Q, qo);
                r = __fsub_rn(r, qo);
                lsum += (double)tq * (double)tq;
            }
            ob[(size_t)d * TT] = Q;
        }
    }

    // ---- deterministic loss partial (reuse s_Ad) ----
    __syncthreads();
    s_Ad[tid] = lsum;
    __syncthreads();
#pragma unroll
    for (int s = 128; s; s >>= 1) {
        if (tid < s) s_Ad[tid] += s_Ad[tid + s];
        __syncthreads();
    }
    if (tid == 0) g_losspart[blockIdx.x] = s_Ad[0];
}

// ---------------- kernel 4: final loss reduction ---------------------------
__global__ void k_loss(float* __restrict__ out) {
    __shared__ double sr[256];
    double s = 0.0;
    for (int i = threadIdx.x; i < NBLK; i += 256) s += g_losspart[i];
    sr[threadIdx.x] = s;
    __syncthreads();
#pragma unroll
    for (int k = 128; k; k >>= 1) {
        if (threadIdx.x < k) sr[threadIdx.x] += sr[threadIdx.x + k];
        __syncthreads();
    }
    if (threadIdx.x == 0)
        out[QO_SIZE + IDX_SIZE] = (float)(sr[0] / (double)QO_SIZE);
}

// ---------------- launch ----------------
extern "C" void kernel_launch(void* const* d_in, const int* in_sizes, int n_in,
                              void* d_out, int out_size) {
    const float* x  = (const float*)d_in[0];   // [32, 512, 1500]
    const float* cb = (const float*)d_in[1];   // [8, 2048, 512]
    float* out = (float*)d_out;

    cudaFuncSetAttribute(k_main, cudaFuncAttributeMaxDynamicSharedMemorySize,
                         SMEM_BYTES);

    k_transpose<<<dim3(KCB / 32, DIMX / 32, NQ), dim3(32, 8)>>>(cb);
    k_cn2<<<(NQ * KCB) / 8, 256>>>(cb);
    k_main<<<NBLK, 256, SMEM_BYTES>>>(x, cb, out);
    k_loss<<<1, 256>>>(out);
}

// round 3
// speedup vs baseline: 1.7055x; 1.7055x over previous
#include <cuda_runtime.h>
#include <math_constants.h>

// ---------------- problem constants ----------------
#define NQ       8
#define KCB      2048
#define DIMX     512
#define BB       32
#define TT       1500
#define NV       (BB * TT)          // 48000 vectors
#define M_TILE   64
#define NBLK     (NV / M_TILE)      // 750 CTAs
#define QO_SIZE  (BB * DIMX * TT)   // 24,576,000
#define IDX_SIZE (BB * NQ * TT)     // 384,000

#define KC_CHUNK 256                // codewords per kc sweep
#define N_KC     (KCB / KC_CHUNK)   // 8
#define D_CHUNK  32                 // dims per epoch
#define N_DC     (DIMX / D_CHUNK)   // 16
#define CBS_FLOATS (D_CHUNK * KC_CHUNK)   // 8192 floats = 32KB per buffer

// smem layout (bytes):
//   resT   [512][64] floats : 131072
//   cbs    2 x 8192  floats :  65536
//   s_Ad   [256]     double :   2048
//   s_A    [64]      float  :    256
//   bestv  [64]      float  :    256
//   besti  [64]      int    :    256
//   s_idx  [8][64]   int    :   2048
#define SMEM_BYTES (131072 + 65536 + 2048 + 256 + 256 + 256 + 2048)

// ---------------- device scratch ----------------
__device__ float  g_cbT[(size_t)NQ * DIMX * KCB];  // codebook [q][d][k]
__device__ float  g_cn2[NQ * KCB];                 // ||c||^2 fp32
__device__ double g_losspart[NBLK];

// ---------------- helpers ----------------
__device__ __forceinline__ void fma2(unsigned long long& d,
                                     unsigned long long a,
                                     unsigned long long b) {
    asm("fma.rn.f32x2 %0, %1, %2, %0;" : "+l"(d) : "l"(a), "l"(b));
}
__device__ __forceinline__ unsigned long long pack2(float x, float y) {
    unsigned long long r;
    asm("mov.b64 %0, {%1, %2};" : "=l"(r) : "f"(x), "f"(y));
    return r;
}
__device__ __forceinline__ void unpack2(unsigned long long v, float& lo, float& hi) {
    asm("mov.b64 {%0, %1}, %2;" : "=f"(lo), "=f"(hi) : "l"(v));
}
__device__ __forceinline__ void cpasync16(unsigned saddr, const void* g) {
    asm volatile("cp.async.cg.shared.global [%0], [%1], 16;"
                 :: "r"(saddr), "l"(g) : "memory");
}
__device__ __forceinline__ void cpasync_commit() {
    asm volatile("cp.async.commit_group;" ::: "memory");
}
__device__ __forceinline__ void cpasync_wait0() {
    asm volatile("cp.async.wait_group 0;" ::: "memory");
}

// ---------------- kernel 1: codebook transpose [q][k][d] -> [q][d][k] ------
__global__ void k_transpose(const float* __restrict__ cb) {
    __shared__ float tile[32][33];
    int q  = blockIdx.z;
    int k0 = blockIdx.x * 32;
    int d0 = blockIdx.y * 32;
    int tx = threadIdx.x, ty = threadIdx.y;
    const float* src = cb + (size_t)q * KCB * DIMX;
#pragma unroll
    for (int i = 0; i < 4; ++i) {
        int k = k0 + ty + i * 8;
        tile[ty + i * 8][tx] = src[(size_t)k * DIMX + d0 + tx];
    }
    __syncthreads();
    float* dst = g_cbT + (size_t)q * DIMX * KCB;
#pragma unroll
    for (int i = 0; i < 4; ++i) {
        int d = d0 + ty + i * 8;
        dst[(size_t)d * KCB + k0 + tx] = tile[tx][ty + i * 8];
    }
}

// ---------------- kernel 2: ||c||^2 (double, one fp32 rounding) ------------
__global__ void k_cn2(const float* __restrict__ cb) {
    int row  = blockIdx.x * 8 + (threadIdx.x >> 5);
    int lane = threadIdx.x & 31;
    const float* src = cb + (size_t)row * DIMX;
    double s = 0.0;
#pragma unroll
    for (int t = 0; t < 16; ++t) {
        double v = (double)src[t * 32 + lane];
        s += v * v;
    }
#pragma unroll
    for (int o = 16; o; o >>= 1)
        s += __shfl_xor_sync(0xffffffffu, s, o);
    if (lane == 0) g_cn2[row] = (float)s;
}

// ---------------- kernel 3: main RVQ -----------------
__global__ void __launch_bounds__(256, 1)
k_main(const float* __restrict__ x, const float* __restrict__ cb,
       float* __restrict__ out) {
    extern __shared__ float sm[];
    float*  resT    = sm;                          // [512][64]
    float*  cbs     = sm + DIMX * M_TILE;          // 2 x [32][256]
    double* s_Ad    = (double*)(cbs + 2 * CBS_FLOATS);
    float*  s_A     = (float*)(s_Ad + 256);        // [64]
    float*  s_bestv = s_A + 64;                    // [64]
    int*    s_besti = (int*)(s_bestv + 64);        // [64]
    int*    s_idx   = s_besti + 64;                // [8][64]

    const int tid  = threadIdx.x;
    const int lane = tid & 31;
    const int wid  = tid >> 5;        // 8 warps x 8 m
    const int n0   = blockIdx.x * M_TILE;
    const int m    = tid & 63;
    const int ds   = tid >> 6;

    const unsigned cbs_u32 =
        (unsigned)__cvta_generic_to_shared((const void*)cbs);

    // ---- init residual = x ----
    {
        int n = n0 + m;
        int b = n / TT;
        int t = n - b * TT;
        const float* xb = x + (size_t)b * DIMX * TT + t;
#pragma unroll 8
        for (int j = 0; j < 128; ++j) {
            int d = ds * 128 + j;
            resT[d * M_TILE + m] = xb[(size_t)d * TT];
        }
    }
    __syncthreads();

#pragma unroll 1
    for (int q = 0; q < NQ; ++q) {
        // ---- A = ||r||^2 (double partials, fixed combine; order-free) ----
        {
            const float* rcol = resT + (size_t)(ds * 128) * M_TILE + m;
            double p = 0.0;
#pragma unroll 8
            for (int j = 0; j < 128; ++j) {
                double v = (double)rcol[j * M_TILE];
                p += v * v;
            }
            s_Ad[tid] = p;
            if (tid < 64) { s_bestv[tid] = CUDART_INF_F; s_besti[tid] = 0; }
        }
        __syncthreads();
        if (tid < 64) {
            double a = ((s_Ad[tid] + s_Ad[64 + tid]) + s_Ad[128 + tid])
                       + s_Ad[192 + tid];
            s_A[tid] = (float)a;
        }
        // s_A consumed only after syncs inside the pipeline below

        const float* cbTq = g_cbT + (size_t)q * DIMX * KCB;
        const float* cn2q = g_cn2 + q * KCB;

#pragma unroll 1
        for (int kc = 0; kc < N_KC; ++kc) {
            const int k0 = kc * KC_CHUNK;
            unsigned long long acc[8][4];          // 8 m x 4 k-pairs (8 k)
#pragma unroll
            for (int i = 0; i < 8; ++i)
#pragma unroll
                for (int j = 0; j < 4; ++j) acc[i][j] = 0ull;

            // prologue: issue loads for dc=0 into buf0
            {
#pragma unroll
                for (int i = 0; i < 8; ++i) {
                    int c   = tid + 256 * i;           // 16B chunk id
                    int row = c >> 6;
                    int col = (c & 63) * 4;
                    cpasync16(cbs_u32 + (unsigned)c * 16,
                              cbTq + (size_t)row * KCB + k0 + col);
                }
                cpasync_commit();
            }

#pragma unroll 1
            for (int dc = 0; dc < N_DC; ++dc) {
                const int cur = dc & 1;
                cpasync_wait0();
                __syncthreads();               // data visible; prev buf free
                if (dc + 1 < N_DC) {           // prefetch next epoch
                    unsigned sb = cbs_u32
                        + (unsigned)(((dc + 1) & 1) * CBS_FLOATS) * 4u;
                    const float* gsrc =
                        cbTq + (size_t)((dc + 1) * D_CHUNK) * KCB + k0;
#pragma unroll
                    for (int i = 0; i < 8; ++i) {
                        int c   = tid + 256 * i;
                        int row = c >> 6;
                        int col = (c & 63) * 4;
                        cpasync16(sb + (unsigned)c * 16,
                                  gsrc + (size_t)row * KCB + col);
                    }
                    cpasync_commit();
                }

                const float* rrow  = resT + (dc * D_CHUNK) * M_TILE + wid * 8;
                const float* ccrow = cbs + cur * CBS_FLOATS + lane * 4;
#pragma unroll 4
                for (int dd = 0; dd < D_CHUNK; ++dd) {
                    const float* rp = rrow + dd * M_TILE;
                    float4 ra = *(const float4*)rp;        // warp broadcast
                    float4 rb = *(const float4*)(rp + 4);
                    unsigned long long rr[8];
                    rr[0] = pack2(ra.x, ra.x); rr[1] = pack2(ra.y, ra.y);
                    rr[2] = pack2(ra.z, ra.z); rr[3] = pack2(ra.w, ra.w);
                    rr[4] = pack2(rb.x, rb.x); rr[5] = pack2(rb.y, rb.y);
                    rr[6] = pack2(rb.z, rb.z); rr[7] = pack2(rb.w, rb.w);

                    const float* cp = ccrow + dd * KC_CHUNK;
                    ulonglong2 cA = *(const ulonglong2*)cp;          // k: L*4..+3
                    ulonglong2 cB = *(const ulonglong2*)(cp + 128);  // k: 128+L*4..
                    unsigned long long cc[4] = {cA.x, cA.y, cB.x, cB.y};
#pragma unroll
                    for (int i = 0; i < 8; ++i)
#pragma unroll
                        for (int j = 0; j < 4; ++j)
                            fma2(acc[i][j], rr[i], cc[j]);
                }
            }

            // ---- finalize: dist = fl(fl(A-2B)+C), running argmin ----
            float4 cnA = *(const float4*)(cn2q + k0 + lane * 4);
            float4 cnB = *(const float4*)(cn2q + k0 + 128 + lane * 4);
            const float cn[8] = {cnA.x, cnA.y, cnA.z, cnA.w,
                                 cnB.x, cnB.y, cnB.z, cnB.w};
            const int kb0 = k0 + lane * 4;        // j=0,1 -> kb0+{0..3}
            const int kb1 = k0 + 128 + lane * 4;  // j=2,3 -> kb1+{0..3}
#pragma unroll
            for (int i = 0; i < 8; ++i) {
                float A  = s_A[wid * 8 + i];
                float bv = CUDART_INF_F;
                int   bi = 0;
#pragma unroll
                for (int j = 0; j < 4; ++j) {
                    float lo, hi;
                    unpack2(acc[i][j], lo, hi);
                    int k = (j < 2 ? kb0 : kb1) + (j & 1) * 2;
                    float v0 = __fadd_rn(__fmaf_rn(-2.0f, lo, A), cn[j * 2]);
                    if (v0 < bv) { bv = v0; bi = k; }
                    float v1 = __fadd_rn(__fmaf_rn(-2.0f, hi, A), cn[j * 2 + 1]);
                    if (v1 < bv) { bv = v1; bi = k + 1; }
                }
#pragma unroll
                for (int o = 16; o; o >>= 1) {
                    float ov = __shfl_xor_sync(0xffffffffu, bv, o);
                    int   oi = __shfl_xor_sync(0xffffffffu, bi, o);
                    if (ov < bv || (ov == bv && oi < bi)) { bv = ov; bi = oi; }
                }
                if (lane == 0) {
                    int mm = wid * 8 + i;         // warp-exclusive slot
                    if (bv < s_bestv[mm]) { s_bestv[mm] = bv; s_besti[mm] = bi; }
                }
            }
        }
        __syncthreads();

        // ---- record + emit indices ----
        if (tid < 64) {
            int n = n0 + tid;
            int b = n / TT;
            int t = n - b * TT;
            int bi = s_besti[tid];
            s_idx[q * 64 + tid] = bi;
            out[QO_SIZE + (size_t)b * NQ * TT + q * TT + t] = (float)bi;
        }
        __syncthreads();

        // ---- exact straight-through residual update ----
        {
            const float* crow = cb + ((size_t)q * KCB + s_idx[q * 64 + m]) * DIMX
                                   + ds * 128;
            float* rcol = resT + (size_t)(ds * 128) * M_TILE + m;
#pragma unroll 4
            for (int j = 0; j < 32; ++j) {
                float4 c4 = *(const float4*)(crow + j * 4);
                int base = (j * 4) * M_TILE;
                float cv[4] = {c4.x, c4.y, c4.z, c4.w};
#pragma unroll
                for (int i = 0; i < 4; ++i) {
                    float r  = rcol[base + i * M_TILE];
                    float t  = __fsub_rn(cv[i], r);
                    float qo = __fadd_rn(r, t);
                    rcol[base + i * M_TILE] = __fsub_rn(r, qo);
                }
            }
        }
        __syncthreads();
    }

    // ---- replay exact ST chain from x: Q, loss ----
    double lsum = 0.0;
    {
        int n = n0 + m;
        int b = n / TT;
        int t = n - b * TT;
        const float* xb = x   + (size_t)b * DIMX * TT + t;
        float*       ob = out + (size_t)b * DIMX * TT + t;
#pragma unroll 2
        for (int j = 0; j < 128; ++j) {
            int d = ds * 128 + j;
            float r = xb[(size_t)d * TT];
            float Q = 0.0f;
#pragma unroll
            for (int q = 0; q < NQ; ++q) {
                float c  = cb[((size_t)q * KCB + s_idx[q * 64 + m]) * DIMX + d];
                float tq = __fsub_rn(c, r);
                float qo = __fadd_rn(r, tq);
                Q = __fadd_rn(Q, qo);
                r = __fsub_rn(r, qo);
                lsum += (double)tq * (double)tq;
            }
            ob[(size_t)d * TT] = Q;
        }
    }

    // ---- deterministic loss partial ----
    __syncthreads();
    s_Ad[tid] = lsum;
    __syncthreads();
#pragma unroll
    for (int s = 128; s; s >>= 1) {
        if (tid < s) s_Ad[tid] += s_Ad[tid + s];
        __syncthreads();
    }
    if (tid == 0) g_losspart[blockIdx.x] = s_Ad[0];
}

// ---------------- kernel 4: final loss reduction ---------------------------
__global__ void k_loss(float* __restrict__ out) {
    __shared__ double sr[256];
    double s = 0.0;
    for (int i = threadIdx.x; i < NBLK; i += 256) s += g_losspart[i];
    sr[threadIdx.x] = s;
    __syncthreads();
#pragma unroll
    for (int k = 128; k; k >>= 1) {
        if (threadIdx.x < k) sr[threadIdx.x] += sr[threadIdx.x + k];
        __syncthreads();
    }
    if (threadIdx.x == 0)
        out[QO_SIZE + IDX_SIZE] = (float)(sr[0] / (double)QO_SIZE);
}

// ---------------- launch ----------------
extern "C" void kernel_launch(void* const* d_in, const int* in_sizes, int n_in,
                              void* d_out, int out_size) {
    const float* x  = (const float*)d_in[0];   // [32, 512, 1500]
    const float* cb = (const float*)d_in[1];   // [8, 2048, 512]
    float* out = (float*)d_out;

    cudaFuncSetAttribute(k_main, cudaFuncAttributeMaxDynamicSharedMemorySize,
                         SMEM_BYTES);

    k_transpose<<<dim3(KCB / 32, DIMX / 32, NQ), dim3(32, 8)>>>(cb);
    k_cn2<<<(NQ * KCB) / 8, 256>>>(cb);
    k_main<<<NBLK, 256, SMEM_BYTES>>>(x, cb, out);
    k_loss<<<1, 256>>>(out);
}

// round 4
// speedup vs baseline: 1.8712x; 1.0972x over previous
#include <cuda_runtime.h>
#include <math_constants.h>

// ---------------- problem constants ----------------
#define NQ       8
#define KCB      2048
#define DIMX     512
#define BB       32
#define TT       1500
#define NV       (BB * TT)          // 48000 vectors
#define M_TILE   48
#define MW       6                  // m-rows per warp (8 warps)
#define NBLK     (NV / M_TILE)      // 1000 CTAs
#define QO_SIZE  (BB * DIMX * TT)   // 24,576,000
#define IDX_SIZE (BB * NQ * TT)     // 384,000

#define KC_CHUNK 256                // codewords per kc sweep
#define N_KC     (KCB / KC_CHUNK)   // 8
#define D_CHUNK  32                 // dims per epoch
#define N_DC     (DIMX / D_CHUNK)   // 16
#define CBS_FLOATS (D_CHUNK * KC_CHUNK)   // 8192 floats = 32KB per buffer

// smem layout (bytes):
//   resT   [512][48] floats :  98304
//   cbs    2 x 8192  floats :  65536
//   s_Ad   [256]     double :   2048
//   s_A    [48]      float  :    192
//   bestv  [48]      float  :    192
//   besti  [48]      int    :    192
//   s_idx  [8][48]   int    :   1536
#define SMEM_BYTES (98304 + 65536 + 2048 + 192 + 192 + 192 + 1536)

// ---------------- device scratch ----------------
__device__ float  g_cbT[(size_t)NQ * DIMX * KCB];  // codebook [q][d][k]
__device__ float  g_cn2[NQ * KCB];                 // ||c||^2 fp32
__device__ double g_losspart[NBLK];

// ---------------- helpers ----------------
__device__ __forceinline__ void fma2(unsigned long long& d,
                                     unsigned long long a,
                                     unsigned long long b) {
    asm("fma.rn.f32x2 %0, %1, %2, %0;" : "+l"(d) : "l"(a), "l"(b));
}
__device__ __forceinline__ unsigned long long pack2(float x, float y) {
    unsigned long long r;
    asm("mov.b64 %0, {%1, %2};" : "=l"(r) : "f"(x), "f"(y));
    return r;
}
__device__ __forceinline__ void unpack2(unsigned long long v, float& lo, float& hi) {
    asm("mov.b64 {%0, %1}, %2;" : "=f"(lo), "=f"(hi) : "l"(v));
}
__device__ __forceinline__ void cpasync16(unsigned saddr, const void* g) {
    asm volatile("cp.async.cg.shared.global [%0], [%1], 16;"
                 :: "r"(saddr), "l"(g) : "memory");
}
__device__ __forceinline__ void cpasync_commit() {
    asm volatile("cp.async.commit_group;" ::: "memory");
}
__device__ __forceinline__ void cpasync_wait0() {
    asm volatile("cp.async.wait_group 0;" ::: "memory");
}

// ---------------- kernel 1: codebook transpose [q][k][d] -> [q][d][k] ------
__global__ void k_transpose(const float* __restrict__ cb) {
    __shared__ float tile[32][33];
    int q  = blockIdx.z;
    int k0 = blockIdx.x * 32;
    int d0 = blockIdx.y * 32;
    int tx = threadIdx.x, ty = threadIdx.y;
    const float* src = cb + (size_t)q * KCB * DIMX;
#pragma unroll
    for (int i = 0; i < 4; ++i) {
        int k = k0 + ty + i * 8;
        tile[ty + i * 8][tx] = src[(size_t)k * DIMX + d0 + tx];
    }
    __syncthreads();
    float* dst = g_cbT + (size_t)q * DIMX * KCB;
#pragma unroll
    for (int i = 0; i < 4; ++i) {
        int d = d0 + ty + i * 8;
        dst[(size_t)d * KCB + k0 + tx] = tile[tx][ty + i * 8];
    }
}

// ---------------- kernel 2: ||c||^2 (double, one fp32 rounding) ------------
__global__ void k_cn2(const float* __restrict__ cb) {
    int row  = blockIdx.x * 8 + (threadIdx.x >> 5);
    int lane = threadIdx.x & 31;
    const float* src = cb + (size_t)row * DIMX;
    double s = 0.0;
#pragma unroll
    for (int t = 0; t < 16; ++t) {
        double v = (double)src[t * 32 + lane];
        s += v * v;
    }
#pragma unroll
    for (int o = 16; o; o >>= 1)
        s += __shfl_xor_sync(0xffffffffu, s, o);
    if (lane == 0) g_cn2[row] = (float)s;
}

// ---------------- kernel 3: main RVQ -----------------
__global__ void __launch_bounds__(256, 1)
k_main(const float* __restrict__ x, const float* __restrict__ cb,
       float* __restrict__ out) {
    extern __shared__ float sm[];
    float*  resT    = sm;                          // [512][48]
    float*  cbs     = sm + DIMX * M_TILE;          // 2 x [32][256]
    double* s_Ad    = (double*)(cbs + 2 * CBS_FLOATS);  // [256]
    float*  s_A     = (float*)(s_Ad + 256);        // [48]
    float*  s_bestv = s_A + M_TILE;                // [48]
    int*    s_besti = (int*)(s_bestv + M_TILE);    // [48]
    int*    s_idx   = s_besti + M_TILE;            // [8][48]

    const int tid  = threadIdx.x;
    const int lane = tid & 31;
    const int wid  = tid >> 5;        // 8 warps x 6 m
    const int n0   = blockIdx.x * M_TILE;

    // elementwise-phase mapping: 5 groups of 48 m-threads (tid<240 active)
    const int g    = tid / M_TILE;            // 0..5 (5 = idle)
    const int m    = tid - g * M_TILE;
    const int dlo  = (g < 5) ? (g * DIMX) / 5 : 0;
    const int dhi  = (g < 5) ? ((g + 1) * DIMX) / 5 : 0;

    const unsigned cbs_u32 =
        (unsigned)__cvta_generic_to_shared((const void*)cbs);

    // ---- init residual = x (transpose gather into smem) ----
    if (g < 5) {
        int n = n0 + m;
        int b = n / TT;
        int t = n - b * TT;
        const float* xb = x + (size_t)b * DIMX * TT + t;
        for (int d = dlo; d < dhi; ++d)
            resT[d * M_TILE + m] = xb[(size_t)d * TT];
    }
    __syncthreads();

#pragma unroll 1
    for (int q = 0; q < NQ; ++q) {
        // ---- A = ||r||^2 (double partials, fixed combine; order-free) ----
        {
            double p = 0.0;
            if (g < 5) {
                const float* rcol = resT + m;
                for (int d = dlo; d < dhi; ++d) {
                    double v = (double)rcol[d * M_TILE];
                    p += v * v;
                }
            }
            s_Ad[tid] = p;
            if (tid < M_TILE) { s_bestv[tid] = CUDART_INF_F; s_besti[tid] = 0; }
        }
        __syncthreads();
        if (tid < M_TILE) {
            double a = ((((s_Ad[tid] + s_Ad[M_TILE + tid])
                        + s_Ad[2 * M_TILE + tid])
                        + s_Ad[3 * M_TILE + tid])
                        + s_Ad[4 * M_TILE + tid]);
            s_A[tid] = (float)a;
        }
        // s_A consumed only after syncs inside the pipeline below

        const float* cbTq = g_cbT + (size_t)q * DIMX * KCB;
        const float* cn2q = g_cn2 + q * KCB;

#pragma unroll 1
        for (int kc = 0; kc < N_KC; ++kc) {
            const int k0 = kc * KC_CHUNK;
            unsigned long long acc[MW][4];         // 6 m x 4 k-pairs (8 k)
#pragma unroll
            for (int i = 0; i < MW; ++i)
#pragma unroll
                for (int j = 0; j < 4; ++j) acc[i][j] = 0ull;

            // prologue: issue loads for dc=0 into buf0
            {
#pragma unroll
                for (int i = 0; i < 8; ++i) {
                    int c   = tid + 256 * i;           // 16B chunk id
                    int row = c >> 6;
                    int col = (c & 63) * 4;
                    cpasync16(cbs_u32 + (unsigned)c * 16,
                              cbTq + (size_t)row * KCB + k0 + col);
                }
                cpasync_commit();
            }

#pragma unroll 1
            for (int dc = 0; dc < N_DC; ++dc) {
                const int cur = dc & 1;
                cpasync_wait0();
                __syncthreads();               // data visible; prev buf free
                if (dc + 1 < N_DC) {           // prefetch next epoch
                    unsigned sb = cbs_u32
                        + (unsigned)(((dc + 1) & 1) * CBS_FLOATS) * 4u;
                    const float* gsrc =
                        cbTq + (size_t)((dc + 1) * D_CHUNK) * KCB + k0;
#pragma unroll
                    for (int i = 0; i < 8; ++i) {
                        int c   = tid + 256 * i;
                        int row = c >> 6;
                        int col = (c & 63) * 4;
                        cpasync16(sb + (unsigned)c * 16,
                                  gsrc + (size_t)row * KCB + col);
                    }
                    cpasync_commit();
                }

                const float* rrow  = resT + (dc * D_CHUNK) * M_TILE + wid * MW;
                const float* ccrow = cbs + cur * CBS_FLOATS + lane * 4;
#pragma unroll 4
                for (int dd = 0; dd < D_CHUNK; ++dd) {
                    const float* rp = rrow + dd * M_TILE;
                    float2 r01 = *(const float2*)rp;       // warp broadcast
                    float2 r23 = *(const float2*)(rp + 2);
                    float2 r45 = *(const float2*)(rp + 4);
                    unsigned long long rr[MW];
                    rr[0] = pack2(r01.x, r01.x); rr[1] = pack2(r01.y, r01.y);
                    rr[2] = pack2(r23.x, r23.x); rr[3] = pack2(r23.y, r23.y);
                    rr[4] = pack2(r45.x, r45.x); rr[5] = pack2(r45.y, r45.y);

                    const float* cp = ccrow + dd * KC_CHUNK;
                    ulonglong2 cA = *(const ulonglong2*)cp;          // k: L*4..
                    ulonglong2 cB = *(const ulonglong2*)(cp + 128);  // k: 128+L*4..
                    unsigned long long cc[4] = {cA.x, cA.y, cB.x, cB.y};
#pragma unroll
                    for (int i = 0; i < MW; ++i)
#pragma unroll
                        for (int j = 0; j < 4; ++j)
                            fma2(acc[i][j], rr[i], cc[j]);
                }
            }

            // ---- finalize: dist = fl(fl(A-2B)+C), running argmin ----
            float4 cnA = *(const float4*)(cn2q + k0 + lane * 4);
            float4 cnB = *(const float4*)(cn2q + k0 + 128 + lane * 4);
            const float cn[8] = {cnA.x, cnA.y, cnA.z, cnA.w,
                                 cnB.x, cnB.y, cnB.z, cnB.w};
            const int kb0 = k0 + lane * 4;        // j=0,1 -> kb0+{0..3}
            const int kb1 = k0 + 128 + lane * 4;  // j=2,3 -> kb1+{0..3}
#pragma unroll
            for (int i = 0; i < MW; ++i) {
                float A  = s_A[wid * MW + i];
                float bv = CUDART_INF_F;
                int   bi = 0;
#pragma unroll
                for (int j = 0; j < 4; ++j) {
                    float lo, hi;
                    unpack2(acc[i][j], lo, hi);
                    int k = (j < 2 ? kb0 : kb1) + (j & 1) * 2;
                    float v0 = __fadd_rn(__fmaf_rn(-2.0f, lo, A), cn[j * 2]);
                    if (v0 < bv) { bv = v0; bi = k; }
                    float v1 = __fadd_rn(__fmaf_rn(-2.0f, hi, A), cn[j * 2 + 1]);
                    if (v1 < bv) { bv = v1; bi = k + 1; }
                }
#pragma unroll
                for (int o = 16; o; o >>= 1) {
                    float ov = __shfl_xor_sync(0xffffffffu, bv, o);
                    int   oi = __shfl_xor_sync(0xffffffffu, bi, o);
                    if (ov < bv || (ov == bv && oi < bi)) { bv = ov; bi = oi; }
                }
                if (lane == 0) {
                    int mm = wid * MW + i;        // warp-exclusive slot
                    if (bv < s_bestv[mm]) { s_bestv[mm] = bv; s_besti[mm] = bi; }
                }
            }
        }
        __syncthreads();

        // ---- record + emit indices ----
        if (tid < M_TILE) {
            int n = n0 + tid;
            int b = n / TT;
            int t = n - b * TT;
            int bi = s_besti[tid];
            s_idx[q * M_TILE + tid] = bi;
            out[QO_SIZE + (size_t)b * NQ * TT + q * TT + t] = (float)bi;
        }
        __syncthreads();

        // ---- exact straight-through residual update ----
        if (g < 5) {
            const float* crow = cb + ((size_t)q * KCB + s_idx[q * M_TILE + m]) * DIMX;
            float* rcol = resT + m;
            for (int d = dlo; d < dhi; ++d) {
                float c  = crow[d];
                float r  = rcol[d * M_TILE];
                float t  = __fsub_rn(c, r);
                float qo = __fadd_rn(r, t);
                rcol[d * M_TILE] = __fsub_rn(r, qo);
            }
        }
        __syncthreads();
    }

    // ---- replay exact ST chain from x: Q, loss ----
    double lsum = 0.0;
    if (g < 5) {
        int n = n0 + m;
        int b = n / TT;
        int t = n - b * TT;
        const float* xb = x   + (size_t)b * DIMX * TT + t;
        float*       ob = out + (size_t)b * DIMX * TT + t;
        for (int d = dlo; d < dhi; ++d) {
            float r = xb[(size_t)d * TT];
            float Q = 0.0f;
#pragma unroll
            for (int q = 0; q < NQ; ++q) {
                float c  = cb[((size_t)q * KCB + s_idx[q * M_TILE + m]) * DIMX + d];
                float tq = __fsub_rn(c, r);
                float qo = __fadd_rn(r, tq);
                Q = __fadd_rn(Q, qo);
                r = __fsub_rn(r, qo);
                lsum += (double)tq * (double)tq;
            }
            ob[(size_t)d * TT] = Q;
        }
    }

    // ---- deterministic loss partial ----
    __syncthreads();
    s_Ad[tid] = lsum;
    __syncthreads();
#pragma unroll
    for (int s = 128; s; s >>= 1) {
        if (tid < s) s_Ad[tid] += s_Ad[tid + s];
        __syncthreads();
    }
    if (tid == 0) g_losspart[blockIdx.x] = s_Ad[0];
}

// ---------------- kernel 4: final loss reduction ---------------------------
__global__ void k_loss(float* __restrict__ out) {
    __shared__ double sr[256];
    double s = 0.0;
    for (int i = threadIdx.x; i < NBLK; i += 256) s += g_losspart[i];
    sr[threadIdx.x] = s;
    __syncthreads();
#pragma unroll
    for (int k = 128; k; k >>= 1) {
        if (threadIdx.x < k) sr[threadIdx.x] += sr[threadIdx.x + k];
        __syncthreads();
    }
    if (threadIdx.x == 0)
        out[QO_SIZE + IDX_SIZE] = (float)(sr[0] / (double)QO_SIZE);
}

// ---------------- launch ----------------
extern "C" void kernel_launch(void* const* d_in, const int* in_sizes, int n_in,
                              void* d_out, int out_size) {
    const float* x  = (const float*)d_in[0];   // [32, 512, 1500]
    const float* cb = (const float*)d_in[1];   // [8, 2048, 512]
    float* out = (float*)d_out;

    cudaFuncSetAttribute(k_main, cudaFuncAttributeMaxDynamicSharedMemorySize,
                         SMEM_BYTES);

    k_transpose<<<dim3(KCB / 32, DIMX / 32, NQ), dim3(32, 8)>>>(cb);
    k_cn2<<<(NQ * KCB) / 8, 256>>>(cb);
    k_main<<<NBLK, 256, SMEM_BYTES>>>(x, cb, out);
    k_loss<<<1, 256>>>(out);
}